// round 9
// baseline (speedup 1.0000x reference)
#include <cuda_runtime.h>
#include <stdint.h>

// VDEmbedding: out[t,:] = (x[t]==0 ? 0 : mask[x[t]]) * weight[x[t], :]
// x: int32 [65536], weight: f32 [128000,128], mask: f32 [128000] -> out: f32 [65536,128]
//
// R8: move the 33.5MB output OFF the per-lane STG/L1tex path. Each warp handles
// 4 consecutive tokens: plain front-batched LDG.128 gathers (proven best load
// path), scale in registers, stage 2KB in smem, then ONE cp.async.bulk
// (TMA/bulk engine, 1D, no tensormap) store of the contiguous 2KB to GMEM.
// Stores stop generating L1tex wavefronts and stop contending with gathers.

static constexpr int EMBED_DIM = 128;
static constexpr int PAD_IDX   = 0;
static constexpr int TOK       = 4;    // tokens per warp (one shot)
static constexpr int WARPS     = 8;    // 256 threads

__global__ __launch_bounds__(256, 8)
void vdemb_kernel(const int* __restrict__ x,
                  const float* __restrict__ weight,
                  const float* __restrict__ mask,
                  float* __restrict__ out,
                  int n_tokens)
{
    __shared__ __align__(16) float stage[WARPS][TOK * EMBED_DIM];  // 8 x 2KB = 16KB

    int warp = threadIdx.x >> 5;
    int lane = threadIdx.x & 31;
    int base = (blockIdx.x * WARPS + warp) * TOK;
    if (base >= n_tokens) return;

    // 1) front-batched index loads
    int idx[TOK];
#pragma unroll
    for (int i = 0; i < TOK; i++) {
        int t = base + i;
        idx[i] = (t < n_tokens) ? __ldg(&x[t]) : PAD_IDX;
    }

    // 2) front-batched mask loads
    float s[TOK];
#pragma unroll
    for (int i = 0; i < TOK; i++)
        s[i] = (idx[i] == PAD_IDX) ? 0.0f : __ldg(&mask[idx[i]]);

    // 3) front-batched row gathers (4 independent LDG.E.128 in flight)
    float4 w[TOK];
#pragma unroll
    for (int i = 0; i < TOK; i++) {
        const float4* wrow =
            reinterpret_cast<const float4*>(weight + (size_t)idx[i] * EMBED_DIM);
        w[i] = __ldg(&wrow[lane]);
    }

    // 4) scale + stage into smem (conflict-free: lanes hit consecutive float4)
#pragma unroll
    for (int i = 0; i < TOK; i++) {
        float4 o;
        o.x = s[i] * w[i].x;
        o.y = s[i] * w[i].y;
        o.z = s[i] * w[i].z;
        o.w = s[i] * w[i].w;
        reinterpret_cast<float4*>(&stage[warp][i * EMBED_DIM])[lane] = o;
    }

    // 5) one bulk store: 4 consecutive tokens = 2KB contiguous in GMEM.
    __syncwarp();
    asm volatile("fence.proxy.async.shared::cta;" ::: "memory");
    if (lane == 0) {
        uint32_t s_addr;
        {
            const void* p = &stage[warp][0];
            asm("{ .reg .u64 t; cvta.to.shared.u64 t, %1; cvt.u32.u64 %0, t; }"
                : "=r"(s_addr) : "l"(p));
        }
        float* dst = out + (size_t)base * EMBED_DIM;
        asm volatile(
            "cp.async.bulk.global.shared::cta.bulk_group [%0], [%1], %2;"
            :: "l"(dst), "r"(s_addr), "n"(TOK * EMBED_DIM * 4)
            : "memory");
        asm volatile("cp.async.bulk.commit_group;" ::: "memory");
        asm volatile("cp.async.bulk.wait_group 0;" ::: "memory");
    }
}

extern "C" void kernel_launch(void* const* d_in, const int* in_sizes, int n_in,
                              void* d_out, int out_size)
{
    const int*   x      = (const int*)d_in[0];
    const float* weight = (const float*)d_in[1];
    const float* mask   = (const float*)d_in[2];
    float*       out    = (float*)d_out;

    int n_tokens = in_sizes[0];                 // 65536
    int tokens_per_block = WARPS * TOK;         // 32
    int blocks = (n_tokens + tokens_per_block - 1) / tokens_per_block;  // 2048

    vdemb_kernel<<<blocks, 256>>>(x, weight, mask, out, n_tokens);
}